// round 3
// baseline (speedup 1.0000x reference)
#include <cuda_runtime.h>
#include <math.h>

typedef unsigned long long u64;

#define NLAYERS 3
#define NWIRES 4

// ---------------------------------------------------------------------------
// Precomputed gate constants.
//  l0[q][0] = row1 (a_re, a_im, b_re, b_im) of layer-0 gate (generic 2x2)
//  l0[q][1] = row2 (c_re, c_im, d_re, d_im)
//  L[l-1][q][0] = (p_re, p_im, cosT, sinT)   p = e^{i phi_eff}
//  L[l-1][q][1] = (o_re, o_im, 0, 0)         o = e^{i om_eff}  (layer 2: unused)
// ---------------------------------------------------------------------------
struct RotConst {
    float4 l0[4][2];
    float4 L[2][4][2];
};
__device__ RotConst g_stage;
__constant__ RotConst c_rot;

__global__ void rot_precompute(const float* __restrict__ params) {
    if (threadIdx.x != 0 || blockIdx.x != 0) return;
    float phi[3][4], th[3][4], om[3][4];
    for (int l = 0; l < 3; ++l)
        for (int q = 0; q < 4; ++q) {
            phi[l][q] = params[(l * 4 + q) * 3 + 0];
            th [l][q] = params[(l * 4 + q) * 3 + 1];
            om [l][q] = params[(l * 4 + q) * 3 + 2];
        }
    // wire-0 phi folds (wire 0 is only ever a CNOT control -> RZ commutes back)
    om[1][0] += phi[2][0]; phi[2][0] = 0.0f;
    float fold10 = phi[1][0]; phi[1][0] = 0.0f;

    // layer 0: generic 2x2 (SU(2) up to global phase), wire-0 gets extra
    // diag(1, e^{i fold10}) applied AFTER it (multiplies row 2).
    for (int q = 0; q < 4; ++q) {
        float s, c;   sincosf(0.5f * th[0][q], &s, &c);
        float sa, ca; sincosf(-0.5f * (phi[0][q] + om[0][q]), &sa, &ca);
        float sb, cb; sincosf( 0.5f * (phi[0][q] - om[0][q]), &sb, &cb);
        float ar =  c * ca, ai =  c * sa;
        float br = -s * cb, bi = -s * sb;
        float cr = -br, ci = bi;        // -conj(b)
        float dr =  ar, di = -ai;       //  conj(a)
        if (q == 0) {
            float sf, cf; sincosf(fold10, &sf, &cf);
            float cr2 = cr * cf - ci * sf, ci2 = cr * sf + ci * cf;
            float dr2 = dr * cf - di * sf, di2 = dr * sf + di * cf;
            cr = cr2; ci = ci2; dr = dr2; di = di2;
        }
        g_stage.l0[q][0] = make_float4(ar, ai, br, bi);
        g_stage.l0[q][1] = make_float4(cr, ci, dr, di);
    }
    // layers 1..2: store (e^{i phi}, cos(th/2), sin(th/2)) and e^{i om}
    for (int l = 1; l < 3; ++l)
        for (int q = 0; q < 4; ++q) {
            float sp, cp; sincosf(phi[l][q], &sp, &cp);
            float s, c;   sincosf(0.5f * th[l][q], &s, &c);
            float so, co; sincosf(om[l][q], &so, &co);
            g_stage.L[l - 1][q][0] = make_float4(cp, sp, c, s);
            g_stage.L[l - 1][q][1] = make_float4(co, so, 0.0f, 0.0f);
        }
}

// ---------------------------------------------------------------------------
// f32x2 packed helpers (Blackwell dual-rate FP32 path)
// ---------------------------------------------------------------------------
__device__ __forceinline__ u64 pk(float lo, float hi) {
    u64 r;
    asm("mov.b64 %0, {%1,%2};" : "=l"(r) : "f"(lo), "f"(hi));
    return r;
}
__device__ __forceinline__ void upk(u64 v, float& lo, float& hi) {
    asm("mov.b64 {%0,%1}, %2;" : "=f"(lo), "=f"(hi) : "l"(v));
}
__device__ __forceinline__ u64 f2mul(u64 a, u64 b) {
    u64 r; asm("mul.rn.f32x2 %0, %1, %2;" : "=l"(r) : "l"(a), "l"(b)); return r;
}
__device__ __forceinline__ u64 f2add(u64 a, u64 b) {
    u64 r; asm("add.rn.f32x2 %0, %1, %2;" : "=l"(r) : "l"(a), "l"(b)); return r;
}
__device__ __forceinline__ u64 f2fma(u64 a, u64 b, u64 c) {
    u64 r; asm("fma.rn.f32x2 %0, %1, %2, %3;" : "=l"(r) : "l"(a), "l"(b), "l"(c)); return r;
}
__device__ __forceinline__ u64 f2sub(u64 a, u64 b) {
    u64 r; asm("sub.rn.f32x2 %0, %1, %2;" : "=l"(r) : "l"(a), "l"(b)); return r;
}
__device__ __forceinline__ u64 f2neg(u64 a) {
    return a ^ 0x8000000080000000ULL;  // sign-bit flip both lanes (ALU pipe)
}

// complex multiply (packed): (cr,ci) = (ar,ai)*(br,bi)
__device__ __forceinline__ void cmul(u64 ar, u64 ai, u64 br, u64 bi, u64& cr, u64& ci) {
    cr = f2fma(ar, br, f2neg(f2mul(ai, bi)));
    ci = f2fma(ar, bi, f2mul(ai, br));
}

// ---------------------------------------------------------------------------
// Full-state diagonal phase: amps with bit M set get multiplied by (pr,pi).
// 8 amps x (2 mul + 2 fma).
// ---------------------------------------------------------------------------
template<int M>
__device__ __forceinline__ void rz_phase(u64* sr, u64* si, u64 pr, u64 pi, u64 npi) {
    #pragma unroll
    for (int i = 0; i < 16; ++i) {
        if (!(i & M)) continue;
        u64 r = f2fma(sr[i], pr, f2mul(si[i], npi));
        si[i] = f2fma(sr[i], pi, f2mul(si[i], pr));
        sr[i] = r;
    }
}

// Full-state real RY rotation on qubit at bit M: 8 pairs x (4 mul + 4 fma).
template<int M>
__device__ __forceinline__ void ry_rot(u64* sr, u64* si, u64 c, u64 s, u64 ns) {
    #pragma unroll
    for (int i = 0; i < 16; ++i) {
        if (i & M) continue;
        const int j = i | M;
        u64 xr = f2fma(c, sr[i], f2mul(ns, sr[j]));
        u64 yr = f2fma(s, sr[i], f2mul(c,  sr[j]));
        u64 xi = f2fma(c, si[i], f2mul(ns, si[j]));
        u64 yi = f2fma(s, si[i], f2mul(c,  si[j]));
        sr[i] = xr; sr[j] = yr; si[i] = xi; si[j] = yi;
    }
}

#define SWAP_AMP(a, b) do { u64 _t = sr[a]; sr[a] = sr[b]; sr[b] = _t; \
                            _t = si[a]; si[a] = si[b]; si[b] = _t; } while (0)

// ---------------------------------------------------------------------------
// Main kernel: each thread simulates 2 batch elements (f32x2 lanes).
// Wire q corresponds to bit (3-q) of the amplitude index (wire 0 = MSB).
// ---------------------------------------------------------------------------
__global__ void __launch_bounds__(256)
qenc_kernel(const float4* __restrict__ x4, float4* __restrict__ out4, int half) {
    int t = blockIdx.x * blockDim.x + threadIdx.x;
    if (t >= half) return;

    float4 xa = x4[t];
    float4 xb = x4[t + half];

    // half-angle trig for the 4 encoding angles, packed over the 2 elements
    u64 tc[4], ts[4];
    {
        float s0, c0, s1, c1;
        __sincosf(0.5f * xa.x, &s0, &c0); __sincosf(0.5f * xb.x, &s1, &c1);
        tc[0] = pk(c0, c1); ts[0] = pk(s0, s1);
        __sincosf(0.5f * xa.y, &s0, &c0); __sincosf(0.5f * xb.y, &s1, &c1);
        tc[1] = pk(c0, c1); ts[1] = pk(s0, s1);
        __sincosf(0.5f * xa.z, &s0, &c0); __sincosf(0.5f * xb.z, &s1, &c1);
        tc[2] = pk(c0, c1); ts[2] = pk(s0, s1);
        __sincosf(0.5f * xa.w, &s0, &c0); __sincosf(0.5f * xb.w, &s1, &c1);
        tc[3] = pk(c0, c1); ts[3] = pk(s0, s1);
    }

    // Encoding + LAYER-0 gate per wire, on product factors:
    //   v_i = G_{0,i} * RY(x_{i+3}) RX(x_{i+2}) RZ(x_{i+1}) RY(x_i) |0>
    u64 vr[4][2], vi[4][2];
    #pragma unroll
    for (int i = 0; i < 4; ++i) {
        u64 c1 = tc[i],           s1 = ts[i];
        u64 c2 = tc[(i + 1) & 3], s2 = ts[(i + 1) & 3];
        u64 c3 = tc[(i + 2) & 3], s3 = ts[(i + 2) & 3];
        u64 c4 = tc[(i + 3) & 3], s4 = ts[(i + 3) & 3];
        // after RY(x_i), RZ(x_{i+1}):  v0 = c1*e^{-i t2/2},  v1 = s1*e^{+i t2/2}
        u64 a_r = f2mul(c1, c2), a_i = f2neg(f2mul(c1, s2));
        u64 b_r = f2mul(s1, c2), b_i = f2mul(s1, s2);
        // RX(x_{i+2}): [[c,-is],[-is,c]]
        u64 ns3 = f2neg(s3);
        u64 w0r = f2fma(c3, a_r, f2mul(s3,  b_i));
        u64 w0i = f2fma(c3, a_i, f2mul(ns3, b_r));
        u64 w1r = f2fma(c3, b_r, f2mul(s3,  a_i));
        u64 w1i = f2fma(c3, b_i, f2mul(ns3, a_r));
        // RY(x_{i+3})
        u64 ns4 = f2neg(s4);
        u64 x0r = f2fma(c4, w0r, f2mul(ns4, w1r));
        u64 x0i = f2fma(c4, w0i, f2mul(ns4, w1i));
        u64 x1r = f2fma(s4, w0r, f2mul(c4,  w1r));
        u64 x1i = f2fma(s4, w0i, f2mul(c4,  w1i));
        // layer-0 generic 2x2 gate (from constant memory, warp-uniform)
        float4 r1 = c_rot.l0[i][0];
        float4 r2 = c_rot.l0[i][1];
        u64 ar = pk(r1.x, r1.x), ai = pk(r1.y, r1.y);
        u64 br = pk(r1.z, r1.z), bi = pk(r1.w, r1.w);
        u64 cr = pk(r2.x, r2.x), ci = pk(r2.y, r2.y);
        u64 dr = pk(r2.z, r2.z), di = pk(r2.w, r2.w);
        vr[i][0] = f2fma(ar, x0r, f2fma(f2neg(ai), x0i, f2fma(br, x1r, f2mul(f2neg(bi), x1i))));
        vi[i][0] = f2fma(ar, x0i, f2fma(ai, x0r,        f2fma(br, x1i, f2mul(bi,        x1r))));
        vr[i][1] = f2fma(cr, x0r, f2fma(f2neg(ci), x0i, f2fma(dr, x1r, f2mul(f2neg(di), x1i))));
        vi[i][1] = f2fma(cr, x0i, f2fma(ci, x0r,        f2fma(dr, x1i, f2mul(di,        x1r))));
    }

    // progressive tensor product -> 16 amplitudes (index = b3 b2 b1 b0, wire0=b3)
    u64 w2r[4], w2i[4], w3r[8], w3i[8], sr[16], si[16];
    #pragma unroll
    for (int k = 0; k < 4; ++k)
        cmul(vr[0][k >> 1], vi[0][k >> 1], vr[1][k & 1], vi[1][k & 1], w2r[k], w2i[k]);
    #pragma unroll
    for (int k = 0; k < 8; ++k)
        cmul(w2r[k >> 1], w2i[k >> 1], vr[2][k & 1], vi[2][k & 1], w3r[k], w3i[k]);
    #pragma unroll
    for (int k = 0; k < 16; ++k)
        cmul(w3r[k >> 1], w3i[k >> 1], vr[3][k & 1], vi[3][k & 1], sr[k], si[k]);

    // layer-0 CNOT chain (pure register permutation, zero SASS)
    SWAP_AMP(8, 12); SWAP_AMP(9, 13); SWAP_AMP(10, 14); SWAP_AMP(11, 15);
    SWAP_AMP(4, 6);  SWAP_AMP(5, 7);  SWAP_AMP(12, 14); SWAP_AMP(13, 15);
    SWAP_AMP(2, 3);  SWAP_AMP(6, 7);  SWAP_AMP(10, 11); SWAP_AMP(14, 15);

    // ----- Layer 1: Rot = RZ(om') RY(th) RZ(phi)   (wire0 phi folded away)
    {
        // wire 0 (mask 8): RY then RZ(om)
        float4 g = c_rot.L[0][0][0];
        float4 h = c_rot.L[0][0][1];
        u64 cc = pk(g.z, g.z), ss = pk(g.w, g.w);
        ry_rot<8>(sr, si, cc, ss, f2neg(ss));
        u64 orr = pk(h.x, h.x), oii = pk(h.y, h.y);
        rz_phase<8>(sr, si, orr, oii, f2neg(oii));
    }
    {
        float4 g = c_rot.L[0][1][0]; float4 h = c_rot.L[0][1][1];
        u64 pr = pk(g.x, g.x), pi = pk(g.y, g.y);
        rz_phase<4>(sr, si, pr, pi, f2neg(pi));
        u64 cc = pk(g.z, g.z), ss = pk(g.w, g.w);
        ry_rot<4>(sr, si, cc, ss, f2neg(ss));
        u64 orr = pk(h.x, h.x), oii = pk(h.y, h.y);
        rz_phase<4>(sr, si, orr, oii, f2neg(oii));
    }
    {
        float4 g = c_rot.L[0][2][0]; float4 h = c_rot.L[0][2][1];
        u64 pr = pk(g.x, g.x), pi = pk(g.y, g.y);
        rz_phase<2>(sr, si, pr, pi, f2neg(pi));
        u64 cc = pk(g.z, g.z), ss = pk(g.w, g.w);
        ry_rot<2>(sr, si, cc, ss, f2neg(ss));
        u64 orr = pk(h.x, h.x), oii = pk(h.y, h.y);
        rz_phase<2>(sr, si, orr, oii, f2neg(oii));
    }
    {
        float4 g = c_rot.L[0][3][0]; float4 h = c_rot.L[0][3][1];
        u64 pr = pk(g.x, g.x), pi = pk(g.y, g.y);
        rz_phase<1>(sr, si, pr, pi, f2neg(pi));
        u64 cc = pk(g.z, g.z), ss = pk(g.w, g.w);
        ry_rot<1>(sr, si, cc, ss, f2neg(ss));
        u64 orr = pk(h.x, h.x), oii = pk(h.y, h.y);
        rz_phase<1>(sr, si, orr, oii, f2neg(oii));
    }
    SWAP_AMP(8, 12); SWAP_AMP(9, 13); SWAP_AMP(10, 14); SWAP_AMP(11, 15);
    SWAP_AMP(4, 6);  SWAP_AMP(5, 7);  SWAP_AMP(12, 14); SWAP_AMP(13, 15);
    SWAP_AMP(2, 3);  SWAP_AMP(6, 7);  SWAP_AMP(10, 11); SWAP_AMP(14, 15);

    // ----- Layer 2: RZ(om) dropped (diagonal before measurement),
    //                wire0 phi folded away -> RY only on wire 0.
    {
        float4 g = c_rot.L[1][0][0];
        u64 cc = pk(g.z, g.z), ss = pk(g.w, g.w);
        ry_rot<8>(sr, si, cc, ss, f2neg(ss));
    }
    {
        float4 g = c_rot.L[1][1][0];
        u64 pr = pk(g.x, g.x), pi = pk(g.y, g.y);
        rz_phase<4>(sr, si, pr, pi, f2neg(pi));
        u64 cc = pk(g.z, g.z), ss = pk(g.w, g.w);
        ry_rot<4>(sr, si, cc, ss, f2neg(ss));
    }
    {
        float4 g = c_rot.L[1][2][0];
        u64 pr = pk(g.x, g.x), pi = pk(g.y, g.y);
        rz_phase<2>(sr, si, pr, pi, f2neg(pi));
        u64 cc = pk(g.z, g.z), ss = pk(g.w, g.w);
        ry_rot<2>(sr, si, cc, ss, f2neg(ss));
    }
    {
        float4 g = c_rot.L[1][3][0];
        u64 pr = pk(g.x, g.x), pi = pk(g.y, g.y);
        rz_phase<1>(sr, si, pr, pi, f2neg(pi));
        u64 cc = pk(g.z, g.z), ss = pk(g.w, g.w);
        ry_rot<1>(sr, si, cc, ss, f2neg(ss));
    }
    SWAP_AMP(8, 12); SWAP_AMP(9, 13); SWAP_AMP(10, 14); SWAP_AMP(11, 15);
    SWAP_AMP(4, 6);  SWAP_AMP(5, 7);  SWAP_AMP(12, 14); SWAP_AMP(13, 15);
    SWAP_AMP(2, 3);  SWAP_AMP(6, 7);  SWAP_AMP(10, 11); SWAP_AMP(14, 15);

    // probabilities: fma(sr,sr, mul(si,si)) — both ops only 2 distinct regs (rt2)
    u64 p[16];
    #pragma unroll
    for (int k = 0; k < 16; ++k)
        p[k] = f2fma(sr[k], sr[k], f2mul(si[k], si[k]));

    // Butterfly (partial Walsh) reduction for the 4 Z expectations.
    u64 a[8], d[8];
    #pragma unroll
    for (int k = 0; k < 8; ++k) {
        a[k] = f2add(p[2 * k], p[2 * k + 1]);
        d[k] = f2sub(p[2 * k], p[2 * k + 1]);
    }
    u64 z3 = f2add(f2add(f2add(d[0], d[1]), f2add(d[2], d[3])),
                   f2add(f2add(d[4], d[5]), f2add(d[6], d[7])));
    u64 b[4], e[4];
    #pragma unroll
    for (int k = 0; k < 4; ++k) {
        b[k] = f2add(a[2 * k], a[2 * k + 1]);
        e[k] = f2sub(a[2 * k], a[2 * k + 1]);
    }
    u64 z2 = f2add(f2add(e[0], e[1]), f2add(e[2], e[3]));
    u64 c0 = f2add(b[0], b[1]), c1 = f2add(b[2], b[3]);
    u64 z1 = f2add(f2sub(b[0], b[1]), f2sub(b[2], b[3]));
    u64 z0 = f2sub(c0, c1);

    float z0a, z0b, z1a, z1b, z2a, z2b, z3a, z3b;
    upk(z0, z0a, z0b); upk(z1, z1a, z1b);
    upk(z2, z2a, z2b); upk(z3, z3a, z3b);
    out4[t]        = make_float4(z0a, z1a, z2a, z3a);
    out4[t + half] = make_float4(z0b, z1b, z2b, z3b);
}

// ---------------------------------------------------------------------------
extern "C" void kernel_launch(void* const* d_in, const int* in_sizes, int n_in,
                              void* d_out, int out_size) {
    const float* x      = (const float*)d_in[0];   // (B, 4) float32
    const float* params = (const float*)d_in[1];   // (3, 4, 3) float32
    float* out          = (float*)d_out;           // (B, 4) float32

    int B = in_sizes[0] / 4;
    int half = B / 2;

    rot_precompute<<<1, 32>>>(params);

    // publish precomputed gate constants into __constant__ memory
    // (D2D memcpy node — graph-capturable)
    void* stage_ptr = nullptr;
    cudaGetSymbolAddress(&stage_ptr, g_stage);
    cudaMemcpyToSymbolAsync(c_rot, stage_ptr, sizeof(RotConst), 0,
                            cudaMemcpyDeviceToDevice);

    int threads = 256;
    int blocks = (half + threads - 1) / threads;
    qenc_kernel<<<blocks, threads>>>((const float4*)x, (float4*)out, half);
}

// round 4
// speedup vs baseline: 1.1635x; 1.1635x over previous
#include <cuda_runtime.h>
#include <math.h>

typedef unsigned long long u64;

// ---------------------------------------------------------------------------
// f32x2 packed helpers (Blackwell dual-rate FP32 path)
// ---------------------------------------------------------------------------
__device__ __forceinline__ u64 pk(float lo, float hi) {
    u64 r;
    asm("mov.b64 %0, {%1,%2};" : "=l"(r) : "f"(lo), "f"(hi));
    return r;
}
__device__ __forceinline__ void upk(u64 v, float& lo, float& hi) {
    asm("mov.b64 {%0,%1}, %2;" : "=f"(lo), "=f"(hi) : "l"(v));
}
__device__ __forceinline__ u64 f2mul(u64 a, u64 b) {
    u64 r; asm("mul.rn.f32x2 %0, %1, %2;" : "=l"(r) : "l"(a), "l"(b)); return r;
}
__device__ __forceinline__ u64 f2add(u64 a, u64 b) {
    u64 r; asm("add.rn.f32x2 %0, %1, %2;" : "=l"(r) : "l"(a), "l"(b)); return r;
}
__device__ __forceinline__ u64 f2fma(u64 a, u64 b, u64 c) {
    u64 r; asm("fma.rn.f32x2 %0, %1, %2, %3;" : "=l"(r) : "l"(a), "l"(b), "l"(c)); return r;
}
__device__ __forceinline__ u64 f2sub(u64 a, u64 b) {
    u64 r; asm("sub.rn.f32x2 %0, %1, %2;" : "=l"(r) : "l"(a), "l"(b)); return r;
}
__device__ __forceinline__ u64 f2neg(u64 a) {
    return a ^ 0x8000000080000000ULL;  // sign-bit flip both lanes (ALU pipe)
}

// complex multiply (packed): (cr,ci) = (ar,ai)*(br,bi)
__device__ __forceinline__ void cmul(u64 ar, u64 ai, u64 br, u64 bi, u64& cr, u64& ci) {
    cr = f2fma(ar, br, f2neg(f2mul(ai, bi)));
    ci = f2fma(ar, bi, f2mul(ai, br));
}

// Full-state real RY rotation on qubit at bit M: 8 pairs x (4 mul + 4 fma).
template<int M>
__device__ __forceinline__ void ry_rot(u64* sr, u64* si, u64 c, u64 s, u64 ns) {
    #pragma unroll
    for (int i = 0; i < 16; ++i) {
        if (i & M) continue;
        const int j = i | M;
        u64 xr = f2fma(c, sr[i], f2mul(ns, sr[j]));
        u64 yr = f2fma(s, sr[i], f2mul(c,  sr[j]));
        u64 xi = f2fma(c, si[i], f2mul(ns, si[j]));
        u64 yi = f2fma(s, si[i], f2mul(c,  si[j]));
        sr[i] = xr; sr[j] = yr; si[i] = xi; si[j] = yi;
    }
}

#define SWAP_AMP(a, b) do { u64 _t = sr[a]; sr[a] = sr[b]; sr[b] = _t; \
                            _t = si[a]; si[a] = si[b]; si[b] = _t; } while (0)

// ---------------------------------------------------------------------------
// Single fused kernel.
// Per-block prologue (warp 0) precomputes all gate constants into smem as
// lane-duplicated u64s; then each thread simulates 2 batch elements packed
// into f32x2 lanes. Wire q = bit (3-q) of the amplitude index (wire0 = MSB).
//
// Circuit (algebraically reduced, diagonals merged):
//   product-state encoding + dense layer-0 gate per wire (wire0 absorbs
//   phi_{1,0} fold), tensor product, CNOT0 (free swaps),
//   D1  = diag(phi_1 on wires 1..3)                      [8 distinct phases]
//   RY(th_1) x4
//   D23 = diag(om_1, incl. wire0 += phi_{2,0}) * CNOT1-pullback(diag(phi_2))
//   CNOT1 (free), RY(th_2) x4, CNOT2 (free), |.|^2, butterfly Z-reduction.
//   (om_2 dropped: trailing diagonals don't change probabilities.)
// ---------------------------------------------------------------------------
__global__ void __launch_bounds__(256)
qenc_kernel(const float4* __restrict__ x4, float4* __restrict__ out4,
            const float* __restrict__ params, int half) {
    __shared__ u64 s_l0[4][8];     // ar ai br bi cr ci dr di (dup)
    __shared__ u64 s_ry[8][2];     // c, s   (gate g = 4*(l-1)+q)
    __shared__ u64 s_d1[8][2];     // pr, pi (index = amp & 7)
    __shared__ u64 s_d23[16][2];   // pr, pi
    __shared__ float2 s_ph[32];    // scratch phasors (cos, sin)

    const int tid = threadIdx.x;

    // ---- Stage A: 31 parallel sincosf into the phasor table -------------
    if (tid < 31) {
        float ang;
        if (tid < 4) {                       // layer0 th/2, wire=tid
            ang = 0.5f * params[tid * 3 + 1];
        } else if (tid < 8) {                // layer0 A = -(phi+om)/2
            int q = tid - 4;
            ang = -0.5f * (params[q * 3 + 0] + params[q * 3 + 2]);
        } else if (tid < 12) {               // layer0 B = (phi-om)/2
            int q = tid - 8;
            ang = 0.5f * (params[q * 3 + 0] - params[q * 3 + 2]);
        } else if (tid == 12) {              // fold10 = phi[1][0]
            ang = params[4 * 3 + 0];
        } else if (tid < 21) {               // RY th/2, layers 1..2
            int idx = tid - 13, l = 1 + (idx >> 2), q = idx & 3;
            ang = 0.5f * params[(l * 4 + q) * 3 + 1];
        } else if (tid < 24) {               // phi[1][q], q=1..3
            int q = tid - 20;
            ang = params[(4 + q) * 3 + 0];
        } else if (tid < 28) {               // om_eff[q] = om[1][q] (+phi[2][0] for q=0)
            int q = tid - 24;
            ang = params[(4 + q) * 3 + 2] + (q == 0 ? params[8 * 3 + 0] : 0.0f);
        } else {                             // phi[2][q], q=1..3
            int q = tid - 27;
            ang = params[(8 + q) * 3 + 0];
        }
        float s, c; sincosf(ang, &s, &c);
        s_ph[tid] = make_float2(c, s);
    }
    __syncthreads();

    // ---- Stage B: assemble gate constants (FFMA only) --------------------
    if (tid < 4) {
        int q = tid;
        float2 T = s_ph[q], A = s_ph[4 + q], Bp = s_ph[8 + q];
        float ar =  T.x * A.x,  ai =  T.x * A.y;
        float br = -T.y * Bp.x, bi = -T.y * Bp.y;
        float cr = -br, ci = bi;   // -conj(b)
        float dr =  ar, di = -ai;  //  conj(a)
        if (q == 0) {              // fold phi[1][0] into row 2
            float2 F = s_ph[12];
            float cr2 = cr * F.x - ci * F.y, ci2 = cr * F.y + ci * F.x;
            float dr2 = dr * F.x - di * F.y, di2 = dr * F.y + di * F.x;
            cr = cr2; ci = ci2; dr = dr2; di = di2;
        }
        s_l0[q][0] = pk(ar, ar); s_l0[q][1] = pk(ai, ai);
        s_l0[q][2] = pk(br, br); s_l0[q][3] = pk(bi, bi);
        s_l0[q][4] = pk(cr, cr); s_l0[q][5] = pk(ci, ci);
        s_l0[q][6] = pk(dr, dr); s_l0[q][7] = pk(di, di);
    } else if (tid < 12) {
        int g = tid - 4;
        float2 T = s_ph[13 + g];
        s_ry[g][0] = pk(T.x, T.x);
        s_ry[g][1] = pk(T.y, T.y);
    } else if (tid == 12) {
        // D1: phases over bits (b2,b1,b0) = wires (1,2,3)
        float2 p1 = s_ph[21], p2 = s_ph[22], p3 = s_ph[23];
        for (int m = 0; m < 8; ++m) {
            float r = 1.0f, im = 0.0f;
            if (m & 4) { r = p1.x; im = p1.y; }
            if (m & 2) { float nr = r * p2.x - im * p2.y, ni = r * p2.y + im * p2.x; r = nr; im = ni; }
            if (m & 1) { float nr = r * p3.x - im * p3.y, ni = r * p3.y + im * p3.x; r = nr; im = ni; }
            s_d1[m][0] = pk(r, r); s_d1[m][1] = pk(im, im);
        }
    } else if (tid == 13) {
        // D23[k] = e^{i om.bits(k)} * e^{i phi2.bits(P(k))},  P = CNOT1 chain
        float2 o0 = s_ph[24], o1 = s_ph[25], o2 = s_ph[26], o3 = s_ph[27];
        float2 q1 = s_ph[28], q2 = s_ph[29], q3 = s_ph[30];
        for (int k = 0; k < 16; ++k) {
            float r = 1.0f, im = 0.0f;
            #define MULP(p) { float nr = r*(p).x - im*(p).y, ni = r*(p).y + im*(p).x; r = nr; im = ni; }
            if (k & 8) MULP(o0);
            if (k & 4) MULP(o1);
            if (k & 2) MULP(o2);
            if (k & 1) MULP(o3);
            int b3 = (k >> 3) & 1, b2 = (k >> 2) & 1, b1 = (k >> 1) & 1, b0 = k & 1;
            int c2 = b2 ^ b3, c1 = b1 ^ c2, c0 = b0 ^ c1;
            if (c2) MULP(q1);
            if (c1) MULP(q2);
            if (c0) MULP(q3);
            #undef MULP
            s_d23[k][0] = pk(r, r); s_d23[k][1] = pk(im, im);
        }
    }
    __syncthreads();

    const int t = blockIdx.x * blockDim.x + tid;
    if (t >= half) return;

    float4 xa = x4[t];
    float4 xb = x4[t + half];

    // half-angle trig for the 4 encoding angles, packed over the 2 elements
    u64 tc[4], ts[4];
    {
        float s0, c0, s1, c1;
        __sincosf(0.5f * xa.x, &s0, &c0); __sincosf(0.5f * xb.x, &s1, &c1);
        tc[0] = pk(c0, c1); ts[0] = pk(s0, s1);
        __sincosf(0.5f * xa.y, &s0, &c0); __sincosf(0.5f * xb.y, &s1, &c1);
        tc[1] = pk(c0, c1); ts[1] = pk(s0, s1);
        __sincosf(0.5f * xa.z, &s0, &c0); __sincosf(0.5f * xb.z, &s1, &c1);
        tc[2] = pk(c0, c1); ts[2] = pk(s0, s1);
        __sincosf(0.5f * xa.w, &s0, &c0); __sincosf(0.5f * xb.w, &s1, &c1);
        tc[3] = pk(c0, c1); ts[3] = pk(s0, s1);
    }

    // Encoding + layer-0 gate per wire, on product factors:
    //   v_i = G_{0,i} * RY(x_{i+3}) RX(x_{i+2}) RZ(x_{i+1}) RY(x_i) |0>
    u64 vr[4][2], vi[4][2];
    #pragma unroll
    for (int i = 0; i < 4; ++i) {
        u64 c1 = tc[i],           s1 = ts[i];
        u64 c2 = tc[(i + 1) & 3], s2 = ts[(i + 1) & 3];
        u64 c3 = tc[(i + 2) & 3], s3 = ts[(i + 2) & 3];
        u64 c4 = tc[(i + 3) & 3], s4 = ts[(i + 3) & 3];
        // after RY(x_i), RZ(x_{i+1}):  v0 = c1*e^{-i t2/2},  v1 = s1*e^{+i t2/2}
        u64 a_r = f2mul(c1, c2), a_i = f2neg(f2mul(c1, s2));
        u64 b_r = f2mul(s1, c2), b_i = f2mul(s1, s2);
        // RX(x_{i+2}): [[c,-is],[-is,c]]
        u64 ns3 = f2neg(s3);
        u64 w0r = f2fma(c3, a_r, f2mul(s3,  b_i));
        u64 w0i = f2fma(c3, a_i, f2mul(ns3, b_r));
        u64 w1r = f2fma(c3, b_r, f2mul(s3,  a_i));
        u64 w1i = f2fma(c3, b_i, f2mul(ns3, a_r));
        // RY(x_{i+3})
        u64 ns4 = f2neg(s4);
        u64 x0r = f2fma(c4, w0r, f2mul(ns4, w1r));
        u64 x0i = f2fma(c4, w0i, f2mul(ns4, w1i));
        u64 x1r = f2fma(s4, w0r, f2mul(c4,  w1r));
        u64 x1i = f2fma(s4, w0i, f2mul(c4,  w1i));
        // layer-0 generic 2x2 gate (smem, warp-uniform broadcast)
        u64 ar = s_l0[i][0], ai = s_l0[i][1], br = s_l0[i][2], bi = s_l0[i][3];
        u64 cr = s_l0[i][4], ci = s_l0[i][5], dr = s_l0[i][6], di = s_l0[i][7];
        vr[i][0] = f2fma(ar, x0r, f2fma(f2neg(ai), x0i, f2fma(br, x1r, f2mul(f2neg(bi), x1i))));
        vi[i][0] = f2fma(ar, x0i, f2fma(ai, x0r,        f2fma(br, x1i, f2mul(bi,        x1r))));
        vr[i][1] = f2fma(cr, x0r, f2fma(f2neg(ci), x0i, f2fma(dr, x1r, f2mul(f2neg(di), x1i))));
        vi[i][1] = f2fma(cr, x0i, f2fma(ci, x0r,        f2fma(dr, x1i, f2mul(di,        x1r))));
    }

    // progressive tensor product -> 16 amplitudes (index = b3 b2 b1 b0)
    u64 w2r[4], w2i[4], w3r[8], w3i[8], sr[16], si[16];
    #pragma unroll
    for (int k = 0; k < 4; ++k)
        cmul(vr[0][k >> 1], vi[0][k >> 1], vr[1][k & 1], vi[1][k & 1], w2r[k], w2i[k]);
    #pragma unroll
    for (int k = 0; k < 8; ++k)
        cmul(w2r[k >> 1], w2i[k >> 1], vr[2][k & 1], vi[2][k & 1], w3r[k], w3i[k]);
    #pragma unroll
    for (int k = 0; k < 16; ++k)
        cmul(w3r[k >> 1], w3i[k >> 1], vr[3][k & 1], vi[3][k & 1], sr[k], si[k]);

    // CNOT0 chain (free register permutation)
    SWAP_AMP(8, 12); SWAP_AMP(9, 13); SWAP_AMP(10, 14); SWAP_AMP(11, 15);
    SWAP_AMP(4, 6);  SWAP_AMP(5, 7);  SWAP_AMP(12, 14); SWAP_AMP(13, 15);
    SWAP_AMP(2, 3);  SWAP_AMP(6, 7);  SWAP_AMP(10, 11); SWAP_AMP(14, 15);

    // D1: merged phi_1 diagonal (amps k and k+8 share a phase; m=0 is identity)
    #pragma unroll
    for (int m = 1; m < 8; ++m) {
        u64 pr = s_d1[m][0], pi = s_d1[m][1], npi = f2neg(pi);
        u64 r = f2fma(sr[m], pr, f2mul(si[m], npi));
        si[m]   = f2fma(sr[m], pi, f2mul(si[m], pr));
        sr[m]   = r;
        r       = f2fma(sr[m + 8], pr, f2mul(si[m + 8], npi));
        si[m+8] = f2fma(sr[m + 8], pi, f2mul(si[m + 8], pr));
        sr[m+8] = r;
    }

    // RY(th_1) on all wires
    { u64 c = s_ry[0][0], s = s_ry[0][1]; ry_rot<8>(sr, si, c, s, f2neg(s)); }
    { u64 c = s_ry[1][0], s = s_ry[1][1]; ry_rot<4>(sr, si, c, s, f2neg(s)); }
    { u64 c = s_ry[2][0], s = s_ry[2][1]; ry_rot<2>(sr, si, c, s, f2neg(s)); }
    { u64 c = s_ry[3][0], s = s_ry[3][1]; ry_rot<1>(sr, si, c, s, f2neg(s)); }

    // D23: merged om_1 + pullback(phi_2) diagonal (k=0 identity)
    #pragma unroll
    for (int k = 1; k < 16; ++k) {
        u64 pr = s_d23[k][0], pi = s_d23[k][1], npi = f2neg(pi);
        u64 r = f2fma(sr[k], pr, f2mul(si[k], npi));
        si[k] = f2fma(sr[k], pi, f2mul(si[k], pr));
        sr[k] = r;
    }

    // CNOT1 chain (free)
    SWAP_AMP(8, 12); SWAP_AMP(9, 13); SWAP_AMP(10, 14); SWAP_AMP(11, 15);
    SWAP_AMP(4, 6);  SWAP_AMP(5, 7);  SWAP_AMP(12, 14); SWAP_AMP(13, 15);
    SWAP_AMP(2, 3);  SWAP_AMP(6, 7);  SWAP_AMP(10, 11); SWAP_AMP(14, 15);

    // RY(th_2) on all wires (om_2 and remaining phases drop before measurement)
    { u64 c = s_ry[4][0], s = s_ry[4][1]; ry_rot<8>(sr, si, c, s, f2neg(s)); }
    { u64 c = s_ry[5][0], s = s_ry[5][1]; ry_rot<4>(sr, si, c, s, f2neg(s)); }
    { u64 c = s_ry[6][0], s = s_ry[6][1]; ry_rot<2>(sr, si, c, s, f2neg(s)); }
    { u64 c = s_ry[7][0], s = s_ry[7][1]; ry_rot<1>(sr, si, c, s, f2neg(s)); }

    // CNOT2 chain (free)
    SWAP_AMP(8, 12); SWAP_AMP(9, 13); SWAP_AMP(10, 14); SWAP_AMP(11, 15);
    SWAP_AMP(4, 6);  SWAP_AMP(5, 7);  SWAP_AMP(12, 14); SWAP_AMP(13, 15);
    SWAP_AMP(2, 3);  SWAP_AMP(6, 7);  SWAP_AMP(10, 11); SWAP_AMP(14, 15);

    // probabilities
    u64 p[16];
    #pragma unroll
    for (int k = 0; k < 16; ++k)
        p[k] = f2fma(sr[k], sr[k], f2mul(si[k], si[k]));

    // Butterfly (partial Walsh) reduction for the 4 Z expectations
    u64 a[8], d[8];
    #pragma unroll
    for (int k = 0; k < 8; ++k) {
        a[k] = f2add(p[2 * k], p[2 * k + 1]);
        d[k] = f2sub(p[2 * k], p[2 * k + 1]);
    }
    u64 z3 = f2add(f2add(f2add(d[0], d[1]), f2add(d[2], d[3])),
                   f2add(f2add(d[4], d[5]), f2add(d[6], d[7])));
    u64 b[4], e[4];
    #pragma unroll
    for (int k = 0; k < 4; ++k) {
        b[k] = f2add(a[2 * k], a[2 * k + 1]);
        e[k] = f2sub(a[2 * k], a[2 * k + 1]);
    }
    u64 z2 = f2add(f2add(e[0], e[1]), f2add(e[2], e[3]));
    u64 c0 = f2add(b[0], b[1]), c1 = f2add(b[2], b[3]);
    u64 z1 = f2add(f2sub(b[0], b[1]), f2sub(b[2], b[3]));
    u64 z0 = f2sub(c0, c1);

    float z0a, z0b, z1a, z1b, z2a, z2b, z3a, z3b;
    upk(z0, z0a, z0b); upk(z1, z1a, z1b);
    upk(z2, z2a, z2b); upk(z3, z3a, z3b);
    out4[t]        = make_float4(z0a, z1a, z2a, z3a);
    out4[t + half] = make_float4(z0b, z1b, z2b, z3b);
}

// ---------------------------------------------------------------------------
extern "C" void kernel_launch(void* const* d_in, const int* in_sizes, int n_in,
                              void* d_out, int out_size) {
    const float* x      = (const float*)d_in[0];   // (B, 4) float32
    const float* params = (const float*)d_in[1];   // (3, 4, 3) float32
    float* out          = (float*)d_out;           // (B, 4) float32

    int B = in_sizes[0] / 4;
    int half = B / 2;

    int threads = 256;
    int blocks = (half + threads - 1) / threads;
    qenc_kernel<<<blocks, threads>>>((const float4*)x, (float4*)out, params, half);
}